// round 15
// baseline (speedup 1.0000x reference)
#include <cuda_runtime.h>
#include <cstdint>

// QuaternionPositionToMatrixLayer: [N,7] f32 -> [N,3,4] f32 pose. Bandwidth-bound;
// measured at the mixed-R/W HBM ceiling (~5.85 TB/s) across four structural variants.
// Champion dataflow (R7): non-persistent, one 256-row tile per CTA.
//   input : coalesced flat float4 LDG (streaming) staged into smem
//   compute: stride-7 LDS (conflict-free), registers
//   output: STS.128 into contiguous smem span, drained by ONE 1D cp.async.bulk
//           (TMA S2G) per CTA — no output STG/LDS wavefronts on the LSU.

constexpr int TPB = 256;   // rows per block == threads per block

__global__ __launch_bounds__(TPB, 8) void quat_pose_kernel(
    const float4* __restrict__ in4,   // flat view of x, N*7 floats
    float4* __restrict__ out4,        // flat view of out, N*12 floats
    int n_rows)
{
    __shared__ __align__(16) float  s_in[TPB * 7];         // 7168 B
    __shared__ __align__(16) float4 s_out[TPB * 3];        // 12288 B

    const int t = threadIdx.x;
    const long long row0 = (long long)blockIdx.x * TPB;
    const int rows_here = min(TPB, n_rows - (int)row0);

    // ---- coalesced staged input: block's span as flat float4s ----
    {
        const long long base4 = row0 * 7 / 4;             // exact: row0 % 4 == 0
        const int nf4 = rows_here * 7 / 4;                // 448 for full blocks
        const int tail_floats = rows_here * 7 - nf4 * 4;  // 0 for full blocks
        float4* s4 = reinterpret_cast<float4*>(s_in);
        #pragma unroll
        for (int i = 0; i < 2; ++i) {
            int idx = t + i * TPB;
            if (idx < nf4) s4[idx] = __ldcs(&in4[base4 + idx]);
        }
        if (tail_floats) {   // generic tail path (not hit for N=4,000,000)
            const float* inf = reinterpret_cast<const float*>(in4);
            for (int k = t; k < tail_floats; k += TPB)
                s_in[nf4 * 4 + k] = inf[row0 * 7 + nf4 * 4 + k];
        }
    }
    __syncthreads();

    // ---- per-row compute (stride-7 smem reads: bank-conflict free) ----
    if (t < rows_here) {
        const float* r = s_in + t * 7;
        const float q0 = r[0], q1 = r[1], q2 = r[2], q3 = r[3];
        const float tx = r[4], ty = r[5], tz = r[6];

        const float q0q0 = q0 * q0, q1q1 = q1 * q1, q2q2 = q2 * q2, q3q3 = q3 * q3;
        const float q0q1 = q0 * q1, q0q2 = q0 * q2, q0q3 = q0 * q3;
        const float q1q2 = q1 * q2, q1q3 = q1 * q3, q2q3 = q2 * q3;

        float4 o0, o1, o2;
        o0.x = q0q0 + q1q1 - q2q2 - q3q3;     // r00
        o0.y = 2.0f * (q1q2 - q0q3);          // r01
        o0.z = 2.0f * (q1q3 + q0q2);          // r02
        o0.w = tx;
        o1.x = 2.0f * (q1q2 + q0q3);          // r10
        o1.y = q0q0 - q1q1 + q2q2 - q3q3;     // r11
        o1.z = 2.0f * (q2q3 - q0q1);          // r12
        o1.w = ty;
        o2.x = 2.0f * (q1q3 - q0q2);          // r20
        o2.y = 2.0f * (q2q3 + q0q1);          // r21
        o2.z = q0q0 - q1q1 - q2q2 + q3q3;     // r22
        o2.w = tz;

        // STS.128 at float4-stride 3 (word stride 12): conflict-free per 8-lane phase.
        s_out[t * 3 + 0] = o0;
        s_out[t * 3 + 1] = o1;
        s_out[t * 3 + 2] = o2;
    }
    __syncthreads();

    // ---- output drain: single 1D TMA bulk store of the contiguous span ----
    // Only t0 issues and holds for read-completion; all other threads are free to
    // retire immediately after the barrier (CTA smem stays live until t0 exits).
    if (t == 0 && rows_here > 0) {
        // Make generic-proxy STS visible to the async (TMA) proxy.
        asm volatile("fence.proxy.async.shared::cta;" ::: "memory");

        unsigned int sout_addr;
        asm("{ .reg .u64 a; cvta.to.shared.u64 a, %1; cvt.u32.u64 %0, a; }"
            : "=r"(sout_addr) : "l"(s_out));
        void* gptr = (void*)(out4 + row0 * 3);
        const unsigned int bytes = (unsigned int)(rows_here * 48);   // multiple of 16

        asm volatile(
            "cp.async.bulk.global.shared::cta.bulk_group [%0], [%1], %2;"
            :: "l"(gptr), "r"(sout_addr), "r"(bytes) : "memory");
        asm volatile("cp.async.bulk.commit_group;" ::: "memory");
        // Smem must stay live until the TMA engine has read it.
        asm volatile("cp.async.bulk.wait_group.read 0;" ::: "memory");
    }
}

extern "C" void kernel_launch(void* const* d_in, const int* in_sizes, int n_in,
                              void* d_out, int out_size)
{
    const float4* in4 = (const float4*)d_in[0];
    float4* out4 = (float4*)d_out;
    const int n_rows = in_sizes[0] / 7;
    const int grid = (n_rows + TPB - 1) / TPB;   // 15625 for N=4M
    quat_pose_kernel<<<grid, TPB>>>(in4, out4, n_rows);
}

// round 16
// speedup vs baseline: 1.0071x; 1.0071x over previous
#include <cuda_runtime.h>
#include <cstdint>

// QuaternionPositionToMatrixLayer: [N,7] f32 -> [N,3,4] f32 pose. Bandwidth-bound
// (~5.8 TB/s mixed-R/W ceiling). This variant: WARP-INDEPENDENT pipelines — zero
// block barriers. Each warp owns 32 rows:
//   lanes load the warp's 56 input float4s (coalesced 896B span) into its private
//   smem region -> __syncwarp -> compute (stride-7 LDS, conflict-free) -> STS.128
//   into the warp's contiguous 1536B output span -> __syncwarp -> lane0 drains the
//   span with its own 1D cp.async.bulk (TMA S2G) and private bulk-group wait.
// Warps never wait on each other; early warps' drains overlap late warps' compute.

constexpr int TPB = 256;            // 8 warps, 32 rows each
constexpr int ROWS_W = 32;          // rows per warp
constexpr int IN_F4_W = ROWS_W * 7 / 4;   // 56 float4 input per warp
constexpr int OUT_F4_W = ROWS_W * 3;      // 96 float4 output per warp

__global__ __launch_bounds__(TPB) void quat_pose_kernel(
    const float4* __restrict__ in4,   // flat view of x, N*7 floats
    float4* __restrict__ out4,        // flat view of out, N*12 floats
    int n_rows)
{
    __shared__ __align__(16) float  s_in[TPB * 7];         // 7168 B (8 x 896B)
    __shared__ __align__(16) float4 s_out[TPB * 3];        // 12288 B (8 x 1536B)

    const int t = threadIdx.x;
    const int w = t >> 5, lane = t & 31;
    const long long wrow0 = (long long)blockIdx.x * TPB + w * ROWS_W;
    const int wrows = min(ROWS_W, (int)(n_rows - wrow0));

    if (wrows == ROWS_W) {
        // ---- warp-private staged input: 56 float4s (rows*28B = 896B, 16B-aligned:
        //      wrow0 % 4 == 0 so wrow0*7 % 4 == 0) ----
        const long long base4 = wrow0 * 7 / 4;
        float4* s4 = reinterpret_cast<float4*>(s_in + w * (ROWS_W * 7));
        s4[lane] = __ldcs(&in4[base4 + lane]);
        if (lane < IN_F4_W - 32)
            s4[lane + 32] = __ldcs(&in4[base4 + lane + 32]);
        __syncwarp();

        // ---- compute (stride-7 LDS within warp region: banks all distinct) ----
        const float* r = s_in + w * (ROWS_W * 7) + lane * 7;
        const float q0 = r[0], q1 = r[1], q2 = r[2], q3 = r[3];
        const float tx = r[4], ty = r[5], tz = r[6];

        const float q0q0 = q0 * q0, q1q1 = q1 * q1, q2q2 = q2 * q2, q3q3 = q3 * q3;
        const float q0q1 = q0 * q1, q0q2 = q0 * q2, q0q3 = q0 * q3;
        const float q1q2 = q1 * q2, q1q3 = q1 * q3, q2q3 = q2 * q3;

        float4 o0, o1, o2;
        o0.x = q0q0 + q1q1 - q2q2 - q3q3;     // r00
        o0.y = 2.0f * (q1q2 - q0q3);          // r01
        o0.z = 2.0f * (q1q3 + q0q2);          // r02
        o0.w = tx;
        o1.x = 2.0f * (q1q2 + q0q3);          // r10
        o1.y = q0q0 - q1q1 + q2q2 - q3q3;     // r11
        o1.z = 2.0f * (q2q3 - q0q1);          // r12
        o1.w = ty;
        o2.x = 2.0f * (q1q3 - q0q2);          // r20
        o2.y = 2.0f * (q2q3 + q0q1);          // r21
        o2.z = q0q0 - q1q1 - q2q2 + q3q3;     // r22
        o2.w = tz;

        // STS.128 at float4-stride 3: per 8-lane phase banks {0,12,24,4,16,28,8,20}.
        float4* so = s_out + w * OUT_F4_W + lane * 3;
        so[0] = o0; so[1] = o1; so[2] = o2;
        __syncwarp();

        // ---- warp drain: one 1D TMA bulk store of the warp's 1536B span ----
        if (lane == 0) {
            asm volatile("fence.proxy.async.shared::cta;" ::: "memory");
            unsigned int sout_addr;
            const float4* sbase = s_out + w * OUT_F4_W;
            asm("{ .reg .u64 a; cvta.to.shared.u64 a, %1; cvt.u32.u64 %0, a; }"
                : "=r"(sout_addr) : "l"(sbase));
            void* gptr = (void*)(out4 + wrow0 * 3);
            asm volatile(
                "cp.async.bulk.global.shared::cta.bulk_group [%0], [%1], %2;"
                :: "l"(gptr), "r"(sout_addr), "n"(OUT_F4_W * 16) : "memory");
            asm volatile("cp.async.bulk.commit_group;" ::: "memory");
            // Smem must stay live until the TMA engine has read this warp's span.
            asm volatile("cp.async.bulk.wait_group.read 0;" ::: "memory");
        }
    } else if (wrows > 0 && lane < wrows) {
        // ---- generic tail (not hit for N=4,000,000): direct global path ----
        const float* rf = reinterpret_cast<const float*>(in4) + (wrow0 + lane) * 7;
        const float q0 = rf[0], q1 = rf[1], q2 = rf[2], q3 = rf[3];
        const float tx = rf[4], ty = rf[5], tz = rf[6];
        const float q0q0 = q0 * q0, q1q1 = q1 * q1, q2q2 = q2 * q2, q3q3 = q3 * q3;
        float* of = reinterpret_cast<float*>(out4) + (wrow0 + lane) * 12;
        of[0]  = q0q0 + q1q1 - q2q2 - q3q3;
        of[1]  = 2.0f * (q1 * q2 - q0 * q3);
        of[2]  = 2.0f * (q1 * q3 + q0 * q2);
        of[3]  = tx;
        of[4]  = 2.0f * (q1 * q2 + q0 * q3);
        of[5]  = q0q0 - q1q1 + q2q2 - q3q3;
        of[6]  = 2.0f * (q2 * q3 - q0 * q1);
        of[7]  = ty;
        of[8]  = 2.0f * (q1 * q3 - q0 * q2);
        of[9]  = 2.0f * (q2 * q3 + q0 * q1);
        of[10] = q0q0 - q1q1 - q2q2 + q3q3;
        of[11] = tz;
    }
}

extern "C" void kernel_launch(void* const* d_in, const int* in_sizes, int n_in,
                              void* d_out, int out_size)
{
    const float4* in4 = (const float4*)d_in[0];
    float4* out4 = (float4*)d_out;
    const int n_rows = in_sizes[0] / 7;
    const int grid = (n_rows + TPB - 1) / TPB;   // 15625 for N=4M
    quat_pose_kernel<<<grid, TPB>>>(in4, out4, n_rows);
}